// round 5
// baseline (speedup 1.0000x reference)
#include <cuda_runtime.h>
#include <cuda_bf16.h>
#include <cstdint>

#define N_TOK  65529
#define NPAD   65536
#define CDIM   1024
#define QKV_N  3072
#define HEADS  16
#define HD     64
#define HDP    68          // padded smem row (bank-conflict mitigation)
#define KTOK   32
#define AW     2           // attention warps per CTA (static smem < 48KB)

// Scratch (allocation-free rule: __device__ global). Attention output is
// written in-place into the Q region of this buffer, so no second buffer.
__device__ float g_qkv[(size_t)NPAD * QKV_N];   // 805 MB
__device__ int   g_idx64;

// ---------------------------------------------------------------------------
// Detect whether batch_idx buffer is int64 (jax x64 on) or int32 (x64 off).
// Sorted, non-negative, small values. For a sorted int32 array,
// x[2i] > 0 && x[2i+1] == 0 is impossible; for an int64 (LE) view it occurs
// well before element N/2. Max index touched: 65527 < 65529.
// ---------------------------------------------------------------------------
__global__ void detect_idx_kernel(const int* __restrict__ b) {
    __shared__ int s;
    if (threadIdx.x == 0) s = 0;
    __syncthreads();
    int local = 0;
    for (int i = threadIdx.x; i < (N_TOK / 2) - 1; i += blockDim.x) {
        int lo = b[2 * i], hi = b[2 * i + 1];
        if (lo > 0 && hi == 0) local = 1;
    }
    if (local) atomicOr(&s, 1);
    __syncthreads();
    if (threadIdx.x == 0) g_idx64 = s;
}

// ---------------------------------------------------------------------------
// fp32 SGEMM, 128x128 block tile, Ktile=8, 256 threads, 8x8 microtile.
// C[row,col] = sum_k A[row*lda + k]*B[k*Nc + col] + bias[col]
//   - rows >= Mreal: A treated as zero, output forced to exactly 0
//   - rows >= MoutRows: not written
// ---------------------------------------------------------------------------
__global__ __launch_bounds__(256) void sgemm_bias(
    const float* __restrict__ A, const float* __restrict__ B,
    const float* __restrict__ bias, float* __restrict__ C,
    int Nc, int Kd, int lda, int ldc, int Mreal, int MoutRows)
{
    __shared__ float As[8][128];
    __shared__ float Bs[8][128];
    const int tid = threadIdx.x;
    const int tx = tid & 15;         // 0..15 -> col microtile
    const int ty = tid >> 4;         // 0..15 -> row microtile
    const int rowBase = blockIdx.y * 128;
    const int colBase = blockIdx.x * 128;

    float acc[8][8];
    #pragma unroll
    for (int i = 0; i < 8; i++)
        #pragma unroll
        for (int j = 0; j < 8; j++) acc[i][j] = 0.0f;

    const int aRow = tid >> 1;            // 128 rows, 2 threads/row
    const int aCol = (tid & 1) * 4;       // 4 floats each
    const int bRow = tid >> 5;            // 8 rows, 32 threads/row
    const int bCol = (tid & 31) * 4;

    for (int k0 = 0; k0 < Kd; k0 += 8) {
        float4 av = make_float4(0.f, 0.f, 0.f, 0.f);
        const int gr = rowBase + aRow;
        if (gr < Mreal)
            av = *(const float4*)&A[(size_t)gr * lda + k0 + aCol];
        As[aCol + 0][aRow] = av.x;
        As[aCol + 1][aRow] = av.y;
        As[aCol + 2][aRow] = av.z;
        As[aCol + 3][aRow] = av.w;

        const float4 bv = *(const float4*)&B[(size_t)(k0 + bRow) * Nc + colBase + bCol];
        *(float4*)&Bs[bRow][bCol] = bv;
        __syncthreads();

        #pragma unroll
        for (int kk = 0; kk < 8; kk++) {
            float4 a0 = *(const float4*)&As[kk][ty * 8];
            float4 a1 = *(const float4*)&As[kk][ty * 8 + 4];
            float4 b0 = *(const float4*)&Bs[kk][tx * 8];
            float4 b1 = *(const float4*)&Bs[kk][tx * 8 + 4];
            float ra[8] = {a0.x, a0.y, a0.z, a0.w, a1.x, a1.y, a1.z, a1.w};
            float rb[8] = {b0.x, b0.y, b0.z, b0.w, b1.x, b1.y, b1.z, b1.w};
            #pragma unroll
            for (int i = 0; i < 8; i++)
                #pragma unroll
                for (int j = 0; j < 8; j++)
                    acc[i][j] = fmaf(ra[i], rb[j], acc[i][j]);
        }
        __syncthreads();
    }

    #pragma unroll
    for (int i = 0; i < 8; i++) {
        const int gr = rowBase + ty * 8 + i;
        if (gr >= MoutRows) continue;
        const bool padRow = (gr >= Mreal);
        #pragma unroll
        for (int j = 0; j < 8; j += 4) {
            const int gc = colBase + tx * 8 + j;
            float4 o;
            o.x = padRow ? 0.f : acc[i][j + 0] + bias[gc + 0];
            o.y = padRow ? 0.f : acc[i][j + 1] + bias[gc + 1];
            o.z = padRow ? 0.f : acc[i][j + 2] + bias[gc + 2];
            o.w = padRow ? 0.f : acc[i][j + 3] + bias[gc + 3];
            *(float4*)&C[(size_t)gr * ldc + gc] = o;
        }
    }
}

// ---------------------------------------------------------------------------
// Attention: AW warps per CTA; each warp handles one (block p, head h) pair.
// Block p, position k -> original row (p>>2)*128 + k*4 + (p&3).
// mask[q][k] = -1000*(batch[q]!=batch[k]) - 1000*(depth[q]<depth[k])
// pad tokens: batch=0, depth=+inf (reproduces reference gmax+1 padding).
// Output written IN-PLACE into the Q region of g_qkv (row*3072 + h*64):
// only this warp ever touches those 64 columns of this row, and it has
// already read Q into registers before writing.
// Static smem: AW*(2*KTOK*HDP + 2*KTOK)*4 = 2*(2*2176+64)*4 = 35,328 B.
// ---------------------------------------------------------------------------
__global__ __launch_bounds__(32 * AW) void attn_kernel(
    const int* __restrict__ bidx, const int* __restrict__ didx)
{
    const int warp = threadIdx.x >> 5;
    const int lane = threadIdx.x & 31;        // query index within block
    const int flat = blockIdx.x * AW + warp;  // 0 .. 2048*16-1
    const int p = flat >> 4;                  // octree block 0..2047
    const int h = flat & 15;                  // head
    const int group = p >> 2;
    const int dsub  = p & 3;
    const int stride = g_idx64 ? 2 : 1;

    __shared__ float ks[AW][KTOK][HDP];
    __shared__ float vs[AW][KTOK][HDP];
    __shared__ int   sb[AW][KTOK];
    __shared__ int   sd[AW][KTOK];

    const int myrow = group * 128 + lane * 4 + dsub;   // < NPAD always

    if (myrow < N_TOK) {
        sb[warp][lane] = bidx[(size_t)myrow * stride];
        sd[warp][lane] = didx[(size_t)myrow * stride];
    } else {
        sb[warp][lane] = 0;
        sd[warp][lane] = 0x40000000;   // bigger than any real depth
    }

    // each lane loads K and V rows for its token (pad rows of g_qkv are zero)
    float* base = &g_qkv[(size_t)myrow * QKV_N];
    {
        const float4* kp = (const float4*)(base + CDIM + h * HD);
        const float4* vp = (const float4*)(base + 2 * CDIM + h * HD);
        #pragma unroll
        for (int i = 0; i < 16; i++) {
            ((float4*)ks[warp][lane])[i] = kp[i];
            ((float4*)vs[warp][lane])[i] = vp[i];
        }
    }
    // Q row in registers
    float4 q[16];
    {
        const float4* qp = (const float4*)(base + h * HD);
        #pragma unroll
        for (int i = 0; i < 16; i++) q[i] = qp[i];
    }
    __syncwarp();

    const int myb = sb[warp][lane];
    const int myd = sd[warp][lane];

    float sc[KTOK];
    float mx = -3.4e38f;
    #pragma unroll
    for (int j = 0; j < KTOK; j++) {
        float4 a4 = make_float4(0.f, 0.f, 0.f, 0.f);
        const float4* kj = (const float4*)ks[warp][j];
        #pragma unroll
        for (int i = 0; i < 16; i++) {
            const float4 kv = kj[i];
            a4.x = fmaf(q[i].x, kv.x, a4.x);
            a4.y = fmaf(q[i].y, kv.y, a4.y);
            a4.z = fmaf(q[i].z, kv.z, a4.z);
            a4.w = fmaf(q[i].w, kv.w, a4.w);
        }
        float s = ((a4.x + a4.y) + (a4.z + a4.w)) * 0.125f;
        if (myb != sb[warp][j]) s -= 1000.0f;
        if (myd <  sd[warp][j]) s -= 1000.0f;
        sc[j] = s;
        mx = fmaxf(mx, s);
    }

    float sum = 0.0f;
    #pragma unroll
    for (int j = 0; j < KTOK; j++) {
        sc[j] = __expf(sc[j] - mx);
        sum += sc[j];
    }
    const float inv = 1.0f / sum;

    float4 o[16];
    #pragma unroll
    for (int i = 0; i < 16; i++) o[i] = make_float4(0.f, 0.f, 0.f, 0.f);
    #pragma unroll
    for (int j = 0; j < KTOK; j++) {
        const float a = sc[j] * inv;
        const float4* vj = (const float4*)vs[warp][j];
        #pragma unroll
        for (int i = 0; i < 16; i++) {
            const float4 vv = vj[i];
            o[i].x = fmaf(a, vv.x, o[i].x);
            o[i].y = fmaf(a, vv.y, o[i].y);
            o[i].z = fmaf(a, vv.z, o[i].z);
            o[i].w = fmaf(a, vv.w, o[i].w);
        }
    }

    // in-place into Q region
    float4* op = (float4*)(base + h * HD);
    #pragma unroll
    for (int i = 0; i < 16; i++) op[i] = o[i];
}

// ---------------------------------------------------------------------------
extern "C" void kernel_launch(void* const* d_in, const int* in_sizes, int n_in,
                              void* d_out, int out_size)
{
    const float* data   = (const float*)d_in[0];
    const float* w_qkv  = (const float*)d_in[1];
    const float* b_qkv  = (const float*)d_in[2];
    const float* w_proj = (const float*)d_in[3];
    const float* b_proj = (const float*)d_in[4];
    const int*   bidx   = (const int*)d_in[5];
    const int*   didx   = (const int*)d_in[6];
    (void)in_sizes; (void)n_in; (void)out_size;

    float* qkv_ptr = nullptr;
    cudaGetSymbolAddress((void**)&qkv_ptr, g_qkv);

    detect_idx_kernel<<<1, 256>>>(bidx);

    // qkv = data @ w_qkv + b_qkv, pad rows -> exact 0
    dim3 g1(QKV_N / 128, NPAD / 128);
    sgemm_bias<<<g1, 256>>>(data, w_qkv, b_qkv, qkv_ptr,
                            QKV_N, CDIM, CDIM, QKV_N, N_TOK, NPAD);

    // blocked attention with on-the-fly octree mask,
    // output written into Q region of g_qkv
    attn_kernel<<<(2048 * HEADS) / AW, 32 * AW>>>(bidx, didx);

    // out = attn_out @ w_proj + b_proj (A = Q region of g_qkv, lda=3072)
    dim3 g2(CDIM / 128, NPAD / 128);
    sgemm_bias<<<g2, 256>>>(qkv_ptr, w_proj, b_proj, (float*)d_out,
                            CDIM, CDIM, QKV_N, CDIM, NPAD, N_TOK);
}

// round 6
// speedup vs baseline: 2.5901x; 2.5901x over previous
#include <cuda_runtime.h>
#include <cuda_bf16.h>
#include <cstdint>

#define N_TOK  65529
#define NPAD   65536
#define CDIM   1024
#define QKV_N  3072
#define HEADS  16
#define HD     64
#define HDP    68
#define KTOK   32
#define AW     2

// A-smem row stride (floats) and B-smem row stride — padded for conflict-free
// mma-fragment loads.
#define ASTR 20
#define BSTR 136

// Scratch (allocation-free rule: __device__ global). Attention output is
// written in-place into the Q region of this buffer.
__device__ float g_qkv[(size_t)NPAD * QKV_N];   // 805 MB
__device__ int   g_idx64;

// ---------------------------------------------------------------------------
__global__ void detect_idx_kernel(const int* __restrict__ b) {
    __shared__ int s;
    if (threadIdx.x == 0) s = 0;
    __syncthreads();
    int local = 0;
    for (int i = threadIdx.x; i < (N_TOK / 2) - 1; i += blockDim.x) {
        int lo = b[2 * i], hi = b[2 * i + 1];
        if (lo > 0 && hi == 0) local = 1;
    }
    if (local) atomicOr(&s, 1);
    __syncthreads();
    if (threadIdx.x == 0) g_idx64 = s;
}

// ---------------------------------------------------------------------------
__device__ __forceinline__ uint32_t f2tf(float f) {
    uint32_t r;
    asm("cvt.rna.tf32.f32 %0, %1;" : "=r"(r) : "f"(f));
    return r;
}

__device__ __forceinline__ void mma_tf32(float* c, const uint32_t* a, const uint32_t* b) {
    asm volatile(
        "mma.sync.aligned.m16n8k8.row.col.f32.tf32.tf32.f32 "
        "{%0,%1,%2,%3}, {%4,%5,%6,%7}, {%8,%9}, {%0,%1,%2,%3};"
        : "+f"(c[0]), "+f"(c[1]), "+f"(c[2]), "+f"(c[3])
        : "r"(a[0]), "r"(a[1]), "r"(a[2]), "r"(a[3]),
          "r"(b[0]), "r"(b[1]));
}

// ---------------------------------------------------------------------------
// TF32 tensor-core GEMM: 128x128 CTA tile, BK=16, 256 threads, 8 warps,
// 64x32 per warp via m16n8k8 fragments. Double-buffered smem, one sync/iter.
// C[row,col] = sum_k A[row*lda+k]*B[k*Nc+col] + bias[col]
//   rows >= Mreal  : A treated as zero, output written as exact 0
//   rows >= MoutRows: not written
// ---------------------------------------------------------------------------
__global__ __launch_bounds__(256) void tf32_gemm(
    const float* __restrict__ A, const float* __restrict__ B,
    const float* __restrict__ bias, float* __restrict__ C,
    int Nc, int Kd, int lda, int ldc, int Mreal, int MoutRows)
{
    __shared__ uint32_t As[2][128 * ASTR];   // 2 x 10240 B
    __shared__ uint32_t Bs[2][16 * BSTR];    // 2 x 8704 B

    const int tid  = threadIdx.x;
    const int warp = tid >> 5;
    const int lane = tid & 31;
    const int wRow = warp >> 2;        // 0..1  (64 rows each)
    const int wCol = warp & 3;         // 0..3  (32 cols each)
    const int g    = lane >> 2;        // 0..7
    const int t4   = lane & 3;         // 0..3
    const int rowBase = blockIdx.y * 128;
    const int colBase = blockIdx.x * 128;

    float acc[4][4][4];
    #pragma unroll
    for (int mt = 0; mt < 4; mt++)
        #pragma unroll
        for (int nt = 0; nt < 4; nt++)
            #pragma unroll
            for (int r = 0; r < 4; r++) acc[mt][nt][r] = 0.0f;

    // gmem staging regs
    float4 sa[2], sb[2];

    const int NT = Kd >> 4;

    auto load_gmem = [&](int kt) {
        #pragma unroll
        for (int i = 0; i < 2; i++) {
            const int vec = tid + i * 256;
            const int ar  = vec >> 2;          // 0..127
            const int ac4 = vec & 3;           // 0..3
            const int gr  = rowBase + ar;
            if (gr < Mreal)
                sa[i] = *(const float4*)&A[(size_t)gr * lda + kt * 16 + ac4 * 4];
            else
                sa[i] = make_float4(0.f, 0.f, 0.f, 0.f);
            const int br  = vec >> 5;          // 0..15
            const int bc4 = vec & 31;          // 0..31
            sb[i] = *(const float4*)&B[(size_t)(kt * 16 + br) * Nc + colBase + bc4 * 4];
        }
    };

    auto store_smem = [&](int buf) {
        #pragma unroll
        for (int i = 0; i < 2; i++) {
            const int vec = tid + i * 256;
            const int ar  = vec >> 2;
            const int ac4 = vec & 3;
            uint32_t* ap = &As[buf][ar * ASTR + ac4 * 4];
            ap[0] = f2tf(sa[i].x); ap[1] = f2tf(sa[i].y);
            ap[2] = f2tf(sa[i].z); ap[3] = f2tf(sa[i].w);
            const int br  = vec >> 5;
            const int bc4 = vec & 31;
            uint32_t* bp = &Bs[buf][br * BSTR + bc4 * 4];
            bp[0] = f2tf(sb[i].x); bp[1] = f2tf(sb[i].y);
            bp[2] = f2tf(sb[i].z); bp[3] = f2tf(sb[i].w);
        }
    };

    load_gmem(0);
    store_smem(0);
    __syncthreads();

    for (int kt = 0; kt < NT; kt++) {
        const int buf = kt & 1;
        if (kt + 1 < NT) load_gmem(kt + 1);

        const uint32_t* Ab = As[buf];
        const uint32_t* Bb = Bs[buf];
        #pragma unroll
        for (int kk = 0; kk < 2; kk++) {
            uint32_t af[4][4];
            uint32_t bf[4][2];
            #pragma unroll
            for (int mt = 0; mt < 4; mt++) {
                const int r = wRow * 64 + mt * 16 + g;
                const int c = kk * 8 + t4;
                af[mt][0] = Ab[r * ASTR + c];
                af[mt][1] = Ab[(r + 8) * ASTR + c];
                af[mt][2] = Ab[r * ASTR + c + 4];
                af[mt][3] = Ab[(r + 8) * ASTR + c + 4];
            }
            #pragma unroll
            for (int nt = 0; nt < 4; nt++) {
                const int n = wCol * 32 + nt * 8 + g;
                const int k = kk * 8 + t4;
                bf[nt][0] = Bb[k * BSTR + n];
                bf[nt][1] = Bb[(k + 4) * BSTR + n];
            }
            #pragma unroll
            for (int mt = 0; mt < 4; mt++)
                #pragma unroll
                for (int nt = 0; nt < 4; nt++)
                    mma_tf32(acc[mt][nt], af[mt], bf[nt]);
        }

        if (kt + 1 < NT) {
            store_smem(buf ^ 1);
            __syncthreads();
        }
    }

    // epilogue
    #pragma unroll
    for (int mt = 0; mt < 4; mt++) {
        #pragma unroll
        for (int half = 0; half < 2; half++) {
            const int gr = rowBase + wRow * 64 + mt * 16 + g + half * 8;
            if (gr >= MoutRows) continue;
            const bool pad = (gr >= Mreal);
            #pragma unroll
            for (int nt = 0; nt < 4; nt++) {
                const int gc = colBase + wCol * 32 + nt * 8 + 2 * t4;
                float2 o;
                o.x = pad ? 0.f : acc[mt][nt][half * 2 + 0] + bias[gc + 0];
                o.y = pad ? 0.f : acc[mt][nt][half * 2 + 1] + bias[gc + 1];
                *(float2*)&C[(size_t)gr * ldc + gc] = o;
            }
        }
    }
}

// ---------------------------------------------------------------------------
// Attention: unchanged from R5 (passed, fp32, in-place output into Q region).
// ---------------------------------------------------------------------------
__global__ __launch_bounds__(32 * AW) void attn_kernel(
    const int* __restrict__ bidx, const int* __restrict__ didx)
{
    const int warp = threadIdx.x >> 5;
    const int lane = threadIdx.x & 31;
    const int flat = blockIdx.x * AW + warp;
    const int p = flat >> 4;
    const int h = flat & 15;
    const int group = p >> 2;
    const int dsub  = p & 3;
    const int stride = g_idx64 ? 2 : 1;

    __shared__ float ks[AW][KTOK][HDP];
    __shared__ float vs[AW][KTOK][HDP];
    __shared__ int   sb_[AW][KTOK];
    __shared__ int   sd_[AW][KTOK];

    const int myrow = group * 128 + lane * 4 + dsub;

    if (myrow < N_TOK) {
        sb_[warp][lane] = bidx[(size_t)myrow * stride];
        sd_[warp][lane] = didx[(size_t)myrow * stride];
    } else {
        sb_[warp][lane] = 0;
        sd_[warp][lane] = 0x40000000;
    }

    float* base = &g_qkv[(size_t)myrow * QKV_N];
    {
        const float4* kp = (const float4*)(base + CDIM + h * HD);
        const float4* vp = (const float4*)(base + 2 * CDIM + h * HD);
        #pragma unroll
        for (int i = 0; i < 16; i++) {
            ((float4*)ks[warp][lane])[i] = kp[i];
            ((float4*)vs[warp][lane])[i] = vp[i];
        }
    }
    float4 q[16];
    {
        const float4* qp = (const float4*)(base + h * HD);
        #pragma unroll
        for (int i = 0; i < 16; i++) q[i] = qp[i];
    }
    __syncwarp();

    const int myb = sb_[warp][lane];
    const int myd = sd_[warp][lane];

    float sc[KTOK];
    float mx = -3.4e38f;
    #pragma unroll
    for (int j = 0; j < KTOK; j++) {
        float4 a4 = make_float4(0.f, 0.f, 0.f, 0.f);
        const float4* kj = (const float4*)ks[warp][j];
        #pragma unroll
        for (int i = 0; i < 16; i++) {
            const float4 kv = kj[i];
            a4.x = fmaf(q[i].x, kv.x, a4.x);
            a4.y = fmaf(q[i].y, kv.y, a4.y);
            a4.z = fmaf(q[i].z, kv.z, a4.z);
            a4.w = fmaf(q[i].w, kv.w, a4.w);
        }
        float s = ((a4.x + a4.y) + (a4.z + a4.w)) * 0.125f;
        if (myb != sb_[warp][j]) s -= 1000.0f;
        if (myd <  sd_[warp][j]) s -= 1000.0f;
        sc[j] = s;
        mx = fmaxf(mx, s);
    }

    float sum = 0.0f;
    #pragma unroll
    for (int j = 0; j < KTOK; j++) {
        sc[j] = __expf(sc[j] - mx);
        sum += sc[j];
    }
    const float inv = 1.0f / sum;

    float4 o[16];
    #pragma unroll
    for (int i = 0; i < 16; i++) o[i] = make_float4(0.f, 0.f, 0.f, 0.f);
    #pragma unroll
    for (int j = 0; j < KTOK; j++) {
        const float a = sc[j] * inv;
        const float4* vj = (const float4*)vs[warp][j];
        #pragma unroll
        for (int i = 0; i < 16; i++) {
            const float4 vv = vj[i];
            o[i].x = fmaf(a, vv.x, o[i].x);
            o[i].y = fmaf(a, vv.y, o[i].y);
            o[i].z = fmaf(a, vv.z, o[i].z);
            o[i].w = fmaf(a, vv.w, o[i].w);
        }
    }

    float4* op = (float4*)(base + h * HD);
    #pragma unroll
    for (int i = 0; i < 16; i++) op[i] = o[i];
}

// ---------------------------------------------------------------------------
extern "C" void kernel_launch(void* const* d_in, const int* in_sizes, int n_in,
                              void* d_out, int out_size)
{
    const float* data   = (const float*)d_in[0];
    const float* w_qkv  = (const float*)d_in[1];
    const float* b_qkv  = (const float*)d_in[2];
    const float* w_proj = (const float*)d_in[3];
    const float* b_proj = (const float*)d_in[4];
    const int*   bidx   = (const int*)d_in[5];
    const int*   didx   = (const int*)d_in[6];
    (void)in_sizes; (void)n_in; (void)out_size;

    float* qkv_ptr = nullptr;
    cudaGetSymbolAddress((void**)&qkv_ptr, g_qkv);

    detect_idx_kernel<<<1, 256>>>(bidx);

    // qkv = data @ w_qkv + b_qkv (tf32 tensor cores), pad rows -> exact 0
    dim3 g1(QKV_N / 128, NPAD / 128);
    tf32_gemm<<<g1, 256>>>(data, w_qkv, b_qkv, qkv_ptr,
                           QKV_N, CDIM, CDIM, QKV_N, N_TOK, NPAD);

    // blocked attention with on-the-fly octree mask, in-place into Q region
    attn_kernel<<<(2048 * HEADS) / AW, 32 * AW>>>(bidx, didx);

    // out = attn_out @ w_proj + b_proj (A = Q region of g_qkv, lda=3072)
    dim3 g2(CDIM / 128, NPAD / 128);
    tf32_gemm<<<g2, 256>>>(qkv_ptr, w_proj, b_proj, (float*)d_out,
                           CDIM, CDIM, QKV_N, CDIM, NPAD, N_TOK);
}

// round 8
// speedup vs baseline: 3.0084x; 1.1615x over previous
#include <cuda_runtime.h>
#include <cuda_bf16.h>
#include <cstdint>

#define N_TOK  65529
#define NPAD   65536
#define CDIM   1024
#define QKV_N  3072
#define HEADS  16
#define HD     64
#define HDP    68
#define KTOK   32
#define AW     2

// gemm config: 128x128 CTA tile, 4 warps, 64x64 per warp, BK=16
#define GT   128
#define ASTR 20
#define BSTR 136

__device__ float g_qkv[(size_t)NPAD * QKV_N];   // 805 MB scratch
__device__ int   g_idx64;

// ---------------------------------------------------------------------------
__global__ void detect_idx_kernel(const int* __restrict__ b) {
    __shared__ int s;
    if (threadIdx.x == 0) s = 0;
    __syncthreads();
    int local = 0;
    for (int i = threadIdx.x; i < (N_TOK / 2) - 1; i += blockDim.x) {
        int lo = b[2 * i], hi = b[2 * i + 1];
        if (lo > 0 && hi == 0) local = 1;
    }
    if (local) atomicOr(&s, 1);
    __syncthreads();
    if (threadIdx.x == 0) g_idx64 = s;
}

// ---------------------------------------------------------------------------
__device__ __forceinline__ uint32_t f2tf(float f) {
    uint32_t r;
    asm("cvt.rna.tf32.f32 %0, %1;" : "=r"(r) : "f"(f));
    return r;
}

__device__ __forceinline__ void mma_tf32(float* c, const uint32_t* a, const uint32_t* b) {
    asm volatile(
        "mma.sync.aligned.m16n8k8.row.col.f32.tf32.tf32.f32 "
        "{%0,%1,%2,%3}, {%4,%5,%6,%7}, {%8,%9}, {%0,%1,%2,%3};"
        : "+f"(c[0]), "+f"(c[1]), "+f"(c[2]), "+f"(c[3])
        : "r"(a[0]), "r"(a[1]), "r"(a[2]), "r"(a[3]),
          "r"(b[0]), "r"(b[1]));
}

// ---------------------------------------------------------------------------
// TF32 tensor-core GEMM: 128x128 CTA tile, BK=16, 128 threads, 4 warps,
// 64x64 per warp via m16n8k8 fragments. Double-buffered smem, one sync/iter.
// C[row,col] = sum_k A[row*lda+k]*B[k*Nc+col] + bias[col]
//   rows >= Mreal  : A treated as zero, output written as exact 0
//   rows >= MoutRows: not written
// ---------------------------------------------------------------------------
__global__ __launch_bounds__(GT, 2) void tf32_gemm(
    const float* __restrict__ A, const float* __restrict__ B,
    const float* __restrict__ bias, float* __restrict__ C,
    int Nc, int Kd, int lda, int ldc, int Mreal, int MoutRows)
{
    __shared__ uint32_t As[2][128 * ASTR];   // 2 x 10240 B
    __shared__ uint32_t Bs[2][16 * BSTR];    // 2 x 8704 B

    const int tid  = threadIdx.x;
    const int warp = tid >> 5;
    const int lane = tid & 31;
    const int wRow = warp >> 1;        // 0..1  (64 rows each)
    const int wCol = warp & 1;         // 0..1  (64 cols each)
    const int g    = lane >> 2;        // 0..7
    const int t4   = lane & 3;         // 0..3
    const int rowBase = blockIdx.y * 128;
    const int colBase = blockIdx.x * 128;

    float acc[4][8][4];
    #pragma unroll
    for (int mt = 0; mt < 4; mt++)
        #pragma unroll
        for (int nt = 0; nt < 8; nt++)
            #pragma unroll
            for (int r = 0; r < 4; r++) acc[mt][nt][r] = 0.0f;

    // gmem staging regs
    float4 sa[4], sb[4];

    const int NT = Kd >> 4;

    auto load_gmem = [&](int kt) {
        #pragma unroll
        for (int i = 0; i < 4; i++) {
            const int vec = tid + i * GT;      // 0..511
            const int ar  = vec >> 2;          // 0..127
            const int ac4 = vec & 3;           // 0..3
            const int gr  = rowBase + ar;
            if (gr < Mreal)
                sa[i] = *(const float4*)&A[(size_t)gr * lda + kt * 16 + ac4 * 4];
            else
                sa[i] = make_float4(0.f, 0.f, 0.f, 0.f);
            const int br  = vec >> 5;          // 0..15
            const int bc4 = vec & 31;          // 0..31
            sb[i] = *(const float4*)&B[(size_t)(kt * 16 + br) * Nc + colBase + bc4 * 4];
        }
    };

    auto store_smem = [&](int buf) {
        #pragma unroll
        for (int i = 0; i < 4; i++) {
            const int vec = tid + i * GT;
            const int ar  = vec >> 2;
            const int ac4 = vec & 3;
            uint32_t* ap = &As[buf][ar * ASTR + ac4 * 4];
            ap[0] = f2tf(sa[i].x); ap[1] = f2tf(sa[i].y);
            ap[2] = f2tf(sa[i].z); ap[3] = f2tf(sa[i].w);
            const int br  = vec >> 5;
            const int bc4 = vec & 31;
            uint32_t* bp = &Bs[buf][br * BSTR + bc4 * 4];
            bp[0] = f2tf(sb[i].x); bp[1] = f2tf(sb[i].y);
            bp[2] = f2tf(sb[i].z); bp[3] = f2tf(sb[i].w);
        }
    };

    load_gmem(0);
    store_smem(0);
    __syncthreads();

    for (int kt = 0; kt < NT; kt++) {
        const int buf = kt & 1;
        if (kt + 1 < NT) load_gmem(kt + 1);

        const uint32_t* Ab = As[buf];
        const uint32_t* Bb = Bs[buf];
        #pragma unroll
        for (int kk = 0; kk < 2; kk++) {
            uint32_t af[4][4];
            uint32_t bf[8][2];
            #pragma unroll
            for (int mt = 0; mt < 4; mt++) {
                const int r = wRow * 64 + mt * 16 + g;
                const int c = kk * 8 + t4;
                af[mt][0] = Ab[r * ASTR + c];
                af[mt][1] = Ab[(r + 8) * ASTR + c];
                af[mt][2] = Ab[r * ASTR + c + 4];
                af[mt][3] = Ab[(r + 8) * ASTR + c + 4];
            }
            #pragma unroll
            for (int nt = 0; nt < 8; nt++) {
                const int n = wCol * 64 + nt * 8 + g;
                const int k = kk * 8 + t4;
                bf[nt][0] = Bb[k * BSTR + n];
                bf[nt][1] = Bb[(k + 4) * BSTR + n];
            }
            #pragma unroll
            for (int mt = 0; mt < 4; mt++)
                #pragma unroll
                for (int nt = 0; nt < 8; nt++)
                    mma_tf32(acc[mt][nt], af[mt], bf[nt]);
        }

        if (kt + 1 < NT) {
            store_smem(buf ^ 1);
            __syncthreads();
        }
    }

    // epilogue
    #pragma unroll
    for (int mt = 0; mt < 4; mt++) {
        #pragma unroll
        for (int half = 0; half < 2; half++) {
            const int gr = rowBase + wRow * 64 + mt * 16 + g + half * 8;
            if (gr >= MoutRows) continue;
            const bool pad = (gr >= Mreal);
            #pragma unroll
            for (int nt = 0; nt < 8; nt++) {
                const int gc = colBase + wCol * 64 + nt * 8 + 2 * t4;
                float2 o;
                o.x = pad ? 0.f : acc[mt][nt][half * 2 + 0] + bias[gc + 0];
                o.y = pad ? 0.f : acc[mt][nt][half * 2 + 1] + bias[gc + 1];
                *(float2*)&C[(size_t)gr * ldc + gc] = o;
            }
        }
    }
}

// ---------------------------------------------------------------------------
// Attention: unchanged (passing since R5). In-place output into Q region.
// ---------------------------------------------------------------------------
__global__ __launch_bounds__(32 * AW) void attn_kernel(
    const int* __restrict__ bidx, const int* __restrict__ didx)
{
    const int warp = threadIdx.x >> 5;
    const int lane = threadIdx.x & 31;
    const int flat = blockIdx.x * AW + warp;
    const int p = flat >> 4;
    const int h = flat & 15;
    const int group = p >> 2;
    const int dsub  = p & 3;
    const int stride = g_idx64 ? 2 : 1;

    __shared__ float ks[AW][KTOK][HDP];
    __shared__ float vs[AW][KTOK][HDP];
    __shared__ int   sb_[AW][KTOK];
    __shared__ int   sd_[AW][KTOK];

    const int myrow = group * 128 + lane * 4 + dsub;

    if (myrow < N_TOK) {
        sb_[warp][lane] = bidx[(size_t)myrow * stride];
        sd_[warp][lane] = didx[(size_t)myrow * stride];
    } else {
        sb_[warp][lane] = 0;
        sd_[warp][lane] = 0x40000000;
    }

    float* base = &g_qkv[(size_t)myrow * QKV_N];
    {
        const float4* kp = (const float4*)(base + CDIM + h * HD);
        const float4* vp = (const float4*)(base + 2 * CDIM + h * HD);
        #pragma unroll
        for (int i = 0; i < 16; i++) {
            ((float4*)ks[warp][lane])[i] = kp[i];
            ((float4*)vs[warp][lane])[i] = vp[i];
        }
    }
    float4 q[16];
    {
        const float4* qp = (const float4*)(base + h * HD);
        #pragma unroll
        for (int i = 0; i < 16; i++) q[i] = qp[i];
    }
    __syncwarp();

    const int myb = sb_[warp][lane];
    const int myd = sd_[warp][lane];

    float sc[KTOK];
    float mx = -3.4e38f;
    #pragma unroll
    for (int j = 0; j < KTOK; j++) {
        float4 a4 = make_float4(0.f, 0.f, 0.f, 0.f);
        const float4* kj = (const float4*)ks[warp][j];
        #pragma unroll
        for (int i = 0; i < 16; i++) {
            const float4 kv = kj[i];
            a4.x = fmaf(q[i].x, kv.x, a4.x);
            a4.y = fmaf(q[i].y, kv.y, a4.y);
            a4.z = fmaf(q[i].z, kv.z, a4.z);
            a4.w = fmaf(q[i].w, kv.w, a4.w);
        }
        float s = ((a4.x + a4.y) + (a4.z + a4.w)) * 0.125f;
        if (myb != sb_[warp][j]) s -= 1000.0f;
        if (myd <  sd_[warp][j]) s -= 1000.0f;
        sc[j] = s;
        mx = fmaxf(mx, s);
    }

    float sum = 0.0f;
    #pragma unroll
    for (int j = 0; j < KTOK; j++) {
        sc[j] = __expf(sc[j] - mx);
        sum += sc[j];
    }
    const float inv = 1.0f / sum;

    float4 o[16];
    #pragma unroll
    for (int i = 0; i < 16; i++) o[i] = make_float4(0.f, 0.f, 0.f, 0.f);
    #pragma unroll
    for (int j = 0; j < KTOK; j++) {
        const float a = sc[j] * inv;
        const float4* vj = (const float4*)vs[warp][j];
        #pragma unroll
        for (int i = 0; i < 16; i++) {
            const float4 vv = vj[i];
            o[i].x = fmaf(a, vv.x, o[i].x);
            o[i].y = fmaf(a, vv.y, o[i].y);
            o[i].z = fmaf(a, vv.z, o[i].z);
            o[i].w = fmaf(a, vv.w, o[i].w);
        }
    }

    float4* op = (float4*)(base + h * HD);
    #pragma unroll
    for (int i = 0; i < 16; i++) op[i] = o[i];
}

// ---------------------------------------------------------------------------
extern "C" void kernel_launch(void* const* d_in, const int* in_sizes, int n_in,
                              void* d_out, int out_size)
{
    const float* data   = (const float*)d_in[0];
    const float* w_qkv  = (const float*)d_in[1];
    const float* b_qkv  = (const float*)d_in[2];
    const float* w_proj = (const float*)d_in[3];
    const float* b_proj = (const float*)d_in[4];
    const int*   bidx   = (const int*)d_in[5];
    const int*   didx   = (const int*)d_in[6];
    (void)in_sizes; (void)n_in; (void)out_size;

    float* qkv_ptr = nullptr;
    cudaGetSymbolAddress((void**)&qkv_ptr, g_qkv);

    detect_idx_kernel<<<1, 256>>>(bidx);

    // qkv = data @ w_qkv + b_qkv (tf32 tensor cores), pad rows -> exact 0
    dim3 g1(QKV_N / 128, NPAD / 128);
    tf32_gemm<<<g1, GT>>>(data, w_qkv, b_qkv, qkv_ptr,
                          QKV_N, CDIM, CDIM, QKV_N, N_TOK, NPAD);

    // blocked attention with on-the-fly octree mask, in-place into Q region
    attn_kernel<<<(2048 * HEADS) / AW, 32 * AW>>>(bidx, didx);

    // out = attn_out @ w_proj + b_proj (A = Q region of g_qkv, lda=3072)
    dim3 g2(CDIM / 128, NPAD / 128);
    tf32_gemm<<<g2, GT>>>(qkv_ptr, w_proj, b_proj, (float*)d_out,
                          CDIM, CDIM, QKV_N, CDIM, NPAD, N_TOK);
}

// round 10
// speedup vs baseline: 3.2264x; 1.0724x over previous
#include <cuda_runtime.h>
#include <cuda_bf16.h>
#include <cstdint>

#define N_TOK  65529
#define NPAD   65536
#define CDIM   1024
#define QKV_N  3072
#define HEADS  16
#define HD     64
#define HDP    68
#define KTOK   32
#define AW     2

// gemm config: 128x128 CTA tile, 4 warps, 64x64 per warp, BK=16
#define GT   128
#define ASTR 20
#define BSTR 136

// Scratch: qkv (attention output overwrites Q region), plus pre-rounded
// tf32 copies of data / w_qkv / w_proj.
#define AUX_DATA  0
#define AUX_WQKV  ((size_t)NPAD * CDIM)
#define AUX_WPROJ (AUX_WQKV + (size_t)CDIM * QKV_N)
#define AUX_TOTAL (AUX_WPROJ + (size_t)CDIM * CDIM)

__device__ float g_qkv[(size_t)NPAD * QKV_N];   // 805 MB
__device__ float g_aux[AUX_TOTAL];              // 285 MB
__device__ int   g_idx64;

// ---------------------------------------------------------------------------
__global__ void detect_idx_kernel(const int* __restrict__ b) {
    __shared__ int s;
    if (threadIdx.x == 0) s = 0;
    __syncthreads();
    int local = 0;
    for (int i = threadIdx.x; i < (N_TOK / 2) - 1; i += blockDim.x) {
        int lo = b[2 * i], hi = b[2 * i + 1];
        if (lo > 0 && hi == 0) local = 1;
    }
    if (local) atomicOr(&s, 1);
    __syncthreads();
    if (threadIdx.x == 0) g_idx64 = s;
}

// ---------------------------------------------------------------------------
__device__ __forceinline__ uint32_t f2tf(float f) {
    uint32_t r;
    asm("cvt.rna.tf32.f32 %0, %1;" : "=r"(r) : "f"(f));
    return r;
}
__device__ __forceinline__ float f2tf_f(float f) {
    return __uint_as_float(f2tf(f));
}

// RNA-round src[0..n4r) into dst; zero dst[n4r..n4t). float4 granularity.
__global__ void round_kernel(const float4* __restrict__ src,
                             float4* __restrict__ dst, int n4r, int n4t)
{
    const int i = blockIdx.x * blockDim.x + threadIdx.x;
    if (i >= n4t) return;
    float4 o = make_float4(0.f, 0.f, 0.f, 0.f);
    if (i < n4r) {
        const float4 v = src[i];
        o.x = f2tf_f(v.x); o.y = f2tf_f(v.y);
        o.z = f2tf_f(v.z); o.w = f2tf_f(v.w);
    }
    dst[i] = o;
}

// ---------------------------------------------------------------------------
__device__ __forceinline__ void mma_tf32(float* c, const uint32_t* a, const uint32_t* b) {
    asm volatile(
        "mma.sync.aligned.m16n8k8.row.col.f32.tf32.tf32.f32 "
        "{%0,%1,%2,%3}, {%4,%5,%6,%7}, {%8,%9}, {%0,%1,%2,%3};"
        : "+f"(c[0]), "+f"(c[1]), "+f"(c[2]), "+f"(c[3])
        : "r"(a[0]), "r"(a[1]), "r"(a[2]), "r"(a[3]),
          "r"(b[0]), "r"(b[1]));
}
__device__ __forceinline__ void cp16(uint32_t saddr, const void* g) {
    asm volatile("cp.async.cg.shared.global [%0], [%1], 16;"
                 :: "r"(saddr), "l"(g) : "memory");
}
__device__ __forceinline__ void cp_commit() {
    asm volatile("cp.async.commit_group;" ::: "memory");
}
__device__ __forceinline__ void cp_wait0() {
    asm volatile("cp.async.wait_group 0;" ::: "memory");
}

// ---------------------------------------------------------------------------
// TF32 tensor-core GEMM: 128x128 CTA tile, BK=16, 128 threads, 4 warps,
// 64x64 per warp. Inputs are PRE-ROUNDED to tf32 (raw bits fed to mma).
// Fill path is cp.async (no register staging, no STS).
// C[row,col] = sum_k A[row*lda+k]*B[k*Nc+col] + bias[col]
//   rows >= Mreal   : output forced to exact 0 (A rows are pre-zeroed)
//   rows >= MoutRows: not written
// ---------------------------------------------------------------------------
__global__ __launch_bounds__(GT, 2) void tf32_gemm(
    const float* __restrict__ A, const float* __restrict__ B,
    const float* __restrict__ bias, float* __restrict__ C,
    int Nc, int Kd, int lda, int ldc, int Mreal, int MoutRows)
{
    __shared__ uint32_t As[2][128 * ASTR];   // 2 x 10240 B
    __shared__ uint32_t Bs[2][16 * BSTR];    // 2 x 8704 B

    const int tid  = threadIdx.x;
    const int warp = tid >> 5;
    const int lane = tid & 31;
    const int wRow = warp >> 1;
    const int wCol = warp & 1;
    const int g    = lane >> 2;
    const int t4   = lane & 3;
    const int rowBase = blockIdx.y * 128;
    const int colBase = blockIdx.x * 128;

    float acc[4][8][4];
    #pragma unroll
    for (int mt = 0; mt < 4; mt++)
        #pragma unroll
        for (int nt = 0; nt < 8; nt++)
            #pragma unroll
            for (int r = 0; r < 4; r++) acc[mt][nt][r] = 0.0f;

    const uint32_t aBase[2] = { (uint32_t)__cvta_generic_to_shared(&As[0][0]),
                                (uint32_t)__cvta_generic_to_shared(&As[1][0]) };
    const uint32_t bBase[2] = { (uint32_t)__cvta_generic_to_shared(&Bs[0][0]),
                                (uint32_t)__cvta_generic_to_shared(&Bs[1][0]) };

    const int NT = Kd >> 4;

    auto fill_async = [&](int buf, int kt) {
        const int k0 = kt * 16;
        #pragma unroll
        for (int i = 0; i < 4; i++) {
            const int vec = tid + i * GT;      // 0..511
            const int ar  = vec >> 2;          // 0..127
            const int ac4 = vec & 3;
            cp16(aBase[buf] + (uint32_t)(ar * ASTR + ac4 * 4) * 4,
                 &A[(size_t)(rowBase + ar) * lda + k0 + ac4 * 4]);
            const int br  = vec >> 5;          // 0..15
            const int bc4 = vec & 31;
            cp16(bBase[buf] + (uint32_t)(br * BSTR + bc4 * 4) * 4,
                 &B[(size_t)(k0 + br) * Nc + colBase + bc4 * 4]);
        }
        cp_commit();
    };

    fill_async(0, 0);
    cp_wait0();
    __syncthreads();

    for (int kt = 0; kt < NT; kt++) {
        const int buf = kt & 1;
        if (kt + 1 < NT) fill_async(buf ^ 1, kt + 1);

        const uint32_t* Ab = As[buf];
        const uint32_t* Bb = Bs[buf];
        #pragma unroll
        for (int kk = 0; kk < 2; kk++) {
            uint32_t af[4][4];
            uint32_t bf[8][2];
            #pragma unroll
            for (int mt = 0; mt < 4; mt++) {
                const int r = wRow * 64 + mt * 16 + g;
                const int c = kk * 8 + t4;
                af[mt][0] = Ab[r * ASTR + c];
                af[mt][1] = Ab[(r + 8) * ASTR + c];
                af[mt][2] = Ab[r * ASTR + c + 4];
                af[mt][3] = Ab[(r + 8) * ASTR + c + 4];
            }
            #pragma unroll
            for (int nt = 0; nt < 8; nt++) {
                const int n = wCol * 64 + nt * 8 + g;
                const int k = kk * 8 + t4;
                bf[nt][0] = Bb[k * BSTR + n];
                bf[nt][1] = Bb[(k + 4) * BSTR + n];
            }
            #pragma unroll
            for (int mt = 0; mt < 4; mt++)
                #pragma unroll
                for (int nt = 0; nt < 8; nt++)
                    mma_tf32(acc[mt][nt], af[mt], bf[nt]);
        }

        if (kt + 1 < NT) {
            cp_wait0();
            __syncthreads();
        }
    }

    // epilogue
    #pragma unroll
    for (int mt = 0; mt < 4; mt++) {
        #pragma unroll
        for (int half = 0; half < 2; half++) {
            const int gr = rowBase + wRow * 64 + mt * 16 + g + half * 8;
            if (gr >= MoutRows) continue;
            const bool pad = (gr >= Mreal);
            #pragma unroll
            for (int nt = 0; nt < 8; nt++) {
                const int gc = colBase + wCol * 64 + nt * 8 + 2 * t4;
                float2 o;
                o.x = pad ? 0.f : acc[mt][nt][half * 2 + 0] + bias[gc + 0];
                o.y = pad ? 0.f : acc[mt][nt][half * 2 + 1] + bias[gc + 1];
                *(float2*)&C[(size_t)gr * ldc + gc] = o;
            }
        }
    }
}

// ---------------------------------------------------------------------------
// Attention: as R8, except the in-place output is RNA-rounded to tf32 so
// GEMM2 can consume it raw (bit-identical to R8's fill-side rounding).
// ---------------------------------------------------------------------------
__global__ __launch_bounds__(32 * AW) void attn_kernel(
    const int* __restrict__ bidx, const int* __restrict__ didx)
{
    const int warp = threadIdx.x >> 5;
    const int lane = threadIdx.x & 31;
    const int flat = blockIdx.x * AW + warp;
    const int p = flat >> 4;
    const int h = flat & 15;
    const int group = p >> 2;
    const int dsub  = p & 3;
    const int stride = g_idx64 ? 2 : 1;

    __shared__ float ks[AW][KTOK][HDP];
    __shared__ float vs[AW][KTOK][HDP];
    __shared__ int   sb_[AW][KTOK];
    __shared__ int   sd_[AW][KTOK];

    const int myrow = group * 128 + lane * 4 + dsub;

    if (myrow < N_TOK) {
        sb_[warp][lane] = bidx[(size_t)myrow * stride];
        sd_[warp][lane] = didx[(size_t)myrow * stride];
    } else {
        sb_[warp][lane] = 0;
        sd_[warp][lane] = 0x40000000;
    }

    float* base = &g_qkv[(size_t)myrow * QKV_N];
    {
        const float4* kp = (const float4*)(base + CDIM + h * HD);
        const float4* vp = (const float4*)(base + 2 * CDIM + h * HD);
        #pragma unroll
        for (int i = 0; i < 16; i++) {
            ((float4*)ks[warp][lane])[i] = kp[i];
            ((float4*)vs[warp][lane])[i] = vp[i];
        }
    }
    float4 q[16];
    {
        const float4* qp = (const float4*)(base + h * HD);
        #pragma unroll
        for (int i = 0; i < 16; i++) q[i] = qp[i];
    }
    __syncwarp();

    const int myb = sb_[warp][lane];
    const int myd = sd_[warp][lane];

    float sc[KTOK];
    float mx = -3.4e38f;
    #pragma unroll
    for (int j = 0; j < KTOK; j++) {
        float4 a4 = make_float4(0.f, 0.f, 0.f, 0.f);
        const float4* kj = (const float4*)ks[warp][j];
        #pragma unroll
        for (int i = 0; i < 16; i++) {
            const float4 kv = kj[i];
            a4.x = fmaf(q[i].x, kv.x, a4.x);
            a4.y = fmaf(q[i].y, kv.y, a4.y);
            a4.z = fmaf(q[i].z, kv.z, a4.z);
            a4.w = fmaf(q[i].w, kv.w, a4.w);
        }
        float s = ((a4.x + a4.y) + (a4.z + a4.w)) * 0.125f;
        if (myb != sb_[warp][j]) s -= 1000.0f;
        if (myd <  sd_[warp][j]) s -= 1000.0f;
        sc[j] = s;
        mx = fmaxf(mx, s);
    }

    float sum = 0.0f;
    #pragma unroll
    for (int j = 0; j < KTOK; j++) {
        sc[j] = __expf(sc[j] - mx);
        sum += sc[j];
    }
    const float inv = 1.0f / sum;

    float4 o[16];
    #pragma unroll
    for (int i = 0; i < 16; i++) o[i] = make_float4(0.f, 0.f, 0.f, 0.f);
    #pragma unroll
    for (int j = 0; j < KTOK; j++) {
        const float a = sc[j] * inv;
        const float4* vj = (const float4*)vs[warp][j];
        #pragma unroll
        for (int i = 0; i < 16; i++) {
            const float4 vv = vj[i];
            o[i].x = fmaf(a, vv.x, o[i].x);
            o[i].y = fmaf(a, vv.y, o[i].y);
            o[i].z = fmaf(a, vv.z, o[i].z);
            o[i].w = fmaf(a, vv.w, o[i].w);
        }
    }

    float4* op = (float4*)(base + h * HD);
    #pragma unroll
    for (int i = 0; i < 16; i++) {
        op[i] = make_float4(f2tf_f(o[i].x), f2tf_f(o[i].y),
                            f2tf_f(o[i].z), f2tf_f(o[i].w));
    }
}

// ---------------------------------------------------------------------------
extern "C" void kernel_launch(void* const* d_in, const int* in_sizes, int n_in,
                              void* d_out, int out_size)
{
    const float* data   = (const float*)d_in[0];
    const float* w_qkv  = (const float*)d_in[1];
    const float* b_qkv  = (const float*)d_in[2];
    const float* w_proj = (const float*)d_in[3];
    const float* b_proj = (const float*)d_in[4];
    const int*   bidx   = (const int*)d_in[5];
    const int*   didx   = (const int*)d_in[6];
    (void)in_sizes; (void)n_in; (void)out_size;

    float* qkv_ptr = nullptr;
    float* aux_ptr = nullptr;
    cudaGetSymbolAddress((void**)&qkv_ptr, g_qkv);
    cudaGetSymbolAddress((void**)&aux_ptr, g_aux);
    float* dataR  = aux_ptr + AUX_DATA;
    float* wqkvR  = aux_ptr + AUX_WQKV;
    float* wprojR = aux_ptr + AUX_WPROJ;

    detect_idx_kernel<<<1, 256>>>(bidx);

    // Pre-round inputs to tf32 (RNA); zero pad rows of data.
    {
        const int n4r = (N_TOK * CDIM) / 4, n4t = (NPAD * CDIM) / 4;
        round_kernel<<<(n4t + 255) / 256, 256>>>((const float4*)data,
                                                 (float4*)dataR, n4r, n4t);
        const int w1 = (CDIM * QKV_N) / 4;
        round_kernel<<<(w1 + 255) / 256, 256>>>((const float4*)w_qkv,
                                                (float4*)wqkvR, w1, w1);
        const int w2 = (CDIM * CDIM) / 4;
        round_kernel<<<(w2 + 255) / 256, 256>>>((const float4*)w_proj,
                                                (float4*)wprojR, w2, w2);
    }

    // qkv = data @ w_qkv + b_qkv, pad rows -> exact 0
    dim3 g1(QKV_N / 128, NPAD / 128);
    tf32_gemm<<<g1, GT>>>(dataR, wqkvR, b_qkv, qkv_ptr,
                          QKV_N, CDIM, CDIM, QKV_N, N_TOK, NPAD);

    // blocked attention; rounded output in-place into Q region
    attn_kernel<<<(2048 * HEADS) / AW, 32 * AW>>>(bidx, didx);

    // out = attn_out @ w_proj + b_proj (A = Q region of g_qkv, lda=3072)
    dim3 g2(CDIM / 128, NPAD / 128);
    tf32_gemm<<<g2, GT>>>(qkv_ptr, wprojR, b_proj, (float*)d_out,
                          CDIM, CDIM, QKV_N, CDIM, NPAD, N_TOK);
}